// round 8
// baseline (speedup 1.0000x reference)
#include <cuda_runtime.h>
#include <math.h>

// Problem sizes
#define Bz 32
#define Sz 512
#define Iz 128
#define Hz 1024
#define Oz 128
#define TPB 256
#define TPBS 512
#define SCAN_GRID 128

typedef unsigned long long u64;

// Scratch (device globals)
__device__ __align__(16) float g_gates[(size_t)3 * Sz * Hz * Bz];   // [gate][t][j][b]
__device__ __align__(16) float g_seq[(size_t)Sz * Hz * Bz];         // [t][j][b]
__device__ __align__(16) float g_h[Hz * Bz];   // paired: [j/2][b][2] -> (j/2)*64 + 2b + (j&1)
__device__ __align__(16) float g_u[Hz * Bz];   // paired, same as g_h
__device__ int   g_bar[2 * Sz];
__device__ int   g_flag[2 * Sz];

__device__ __forceinline__ float sigmoidf_(float x) {
    return 1.0f / (1.0f + expf(-x));
}

// packed fp32x2 FMA: acc = a * b + acc
__device__ __forceinline__ void ffma2(u64& acc, u64 a, u64 b) {
    asm("fma.rn.f32x2 %0, %1, %2, %0;" : "+l"(acc) : "l"(a), "l"(b));
}
__device__ __forceinline__ float f2sum(u64 v) {
    float lo, hi;
    asm("mov.b64 {%0, %1}, %2;" : "=f"(lo), "=f"(hi) : "l"(v));
    return lo + hi;
}

// cp.async 16B, L1-bypass (.cg)
__device__ __forceinline__ void cpa16(unsigned s, const void* g) {
    asm volatile("cp.async.cg.shared.global [%0], [%1], 16;" :: "r"(s), "l"(g));
}
__device__ __forceinline__ void cpa_commit() {
    asm volatile("cp.async.commit_group;" ::: "memory");
}
template <int N>
__device__ __forceinline__ void cpa_wait() {
    asm volatile("cp.async.wait_group %0;" :: "n"(N) : "memory");
}

// Fence-free grid barrier: release-atomic arrive, single-writer release flag,
// acquire spin. All cross-CTA data reads bypass L1 (cp.async.cg).
__device__ __forceinline__ void grid_bar(int i, int ncta) {
    __syncthreads();
    if (threadIdx.x == 0) {
        int v;
        asm volatile("atom.release.gpu.global.add.s32 %0, [%1], 1;"
                     : "=r"(v) : "l"(&g_bar[i]) : "memory");
        if (v == ncta - 1) {
            asm volatile("st.release.gpu.global.s32 [%0], 1;"
                         :: "l"(&g_flag[i]) : "memory");
        } else {
            int f;
            do {
                asm volatile("ld.acquire.gpu.global.s32 %0, [%1];"
                             : "=r"(f) : "l"(&g_flag[i]) : "memory");
            } while (f == 0);
        }
    }
    __syncthreads();
}

// ---------------------------------------------------------------------------
// prep: init h state (paired layout) + zero barrier counters/flags
// ---------------------------------------------------------------------------
__global__ void prep_kernel(const float* __restrict__ h0, int layer) {
    int idx = blockIdx.x * TPB + threadIdx.x;
    int j = idx >> 5;
    int b = idx & 31;
    g_h[(j >> 1) * 64 + 2 * b + (j & 1)] = h0[b * (2 * Hz) + layer * Hz + j];
    if (idx < 2 * Sz) { g_bar[idx] = 0; g_flag[idx] = 0; }
}

// ---------------------------------------------------------------------------
// proj0: layer-0 input projections (K=128)
// ---------------------------------------------------------------------------
__global__ void __launch_bounds__(TPB) proj0_kernel(
    const float* __restrict__ x,
    const float* __restrict__ Wz, const float* __restrict__ Wr, const float* __restrict__ Wg)
{
    __shared__ float xs[Iz * 33];
    const int s = blockIdx.x;
    const int tid = threadIdx.x, lane = tid & 31, w = tid >> 5;

    #pragma unroll
    for (int rep = 0; rep < 16; ++rep) {
        int e = rep * 256 + tid;
        int b = e >> 7, i = e & 127;
        xs[i * 33 + b] = x[((size_t)b * Sz + s) * Iz + i];
    }
    __syncthreads();

    for (int c = 0; c < 96; ++c) {
        int rr = w * 384 + c * 4;
        int g = rr >> 10;
        int j = rr & 1023;
        const float* Wp = (g == 0) ? Wz : ((g == 1) ? Wr : Wg);
        const float4* w0 = (const float4*)(Wp + (size_t)(j + 0) * Iz);
        const float4* w1 = (const float4*)(Wp + (size_t)(j + 1) * Iz);
        const float4* w2 = (const float4*)(Wp + (size_t)(j + 2) * Iz);
        const float4* w3 = (const float4*)(Wp + (size_t)(j + 3) * Iz);
        float a0 = 0.f, a1 = 0.f, a2 = 0.f, a3 = 0.f;
        #pragma unroll 8
        for (int i4 = 0; i4 < 32; ++i4) {
            float h0v = xs[(i4 * 4 + 0) * 33 + lane];
            float h1v = xs[(i4 * 4 + 1) * 33 + lane];
            float h2v = xs[(i4 * 4 + 2) * 33 + lane];
            float h3v = xs[(i4 * 4 + 3) * 33 + lane];
            float4 q0 = w0[i4], q1 = w1[i4], q2 = w2[i4], q3 = w3[i4];
            a0 = fmaf(q0.x, h0v, a0); a0 = fmaf(q0.y, h1v, a0); a0 = fmaf(q0.z, h2v, a0); a0 = fmaf(q0.w, h3v, a0);
            a1 = fmaf(q1.x, h0v, a1); a1 = fmaf(q1.y, h1v, a1); a1 = fmaf(q1.z, h2v, a1); a1 = fmaf(q1.w, h3v, a1);
            a2 = fmaf(q2.x, h0v, a2); a2 = fmaf(q2.y, h1v, a2); a2 = fmaf(q2.z, h2v, a2); a2 = fmaf(q2.w, h3v, a2);
            a3 = fmaf(q3.x, h0v, a3); a3 = fmaf(q3.y, h1v, a3); a3 = fmaf(q3.z, h2v, a3); a3 = fmaf(q3.w, h3v, a3);
        }
        size_t base = (((size_t)g * Sz + s) * Hz + j) * Bz + lane;
        g_gates[base +  0] = a0;
        g_gates[base + 32] = a1;
        g_gates[base + 64] = a2;
        g_gates[base + 96] = a3;
    }
}

// ---------------------------------------------------------------------------
// proj1: layer-1 input projections (K=1024) from g_seq
// ---------------------------------------------------------------------------
__global__ void __launch_bounds__(TPB) proj1_kernel(
    const float* __restrict__ Wz, const float* __restrict__ Wr, const float* __restrict__ Wg)
{
    __shared__ float xs[256 * 33];
    const int s = blockIdx.y;
    const int rb = blockIdx.x;
    const int tid = threadIdx.x, lane = tid & 31, w = tid >> 5;

    float acc[48];
    #pragma unroll
    for (int q = 0; q < 48; ++q) acc[q] = 0.f;

    for (int kt = 0; kt < 4; ++kt) {
        __syncthreads();
        #pragma unroll
        for (int rep = 0; rep < 32; ++rep) {
            int e = rep * 256 + tid;
            int i = e >> 5, b = e & 31;
            xs[i * 33 + b] = g_seq[((size_t)s * Hz + kt * 256 + i) * Bz + b];
        }
        __syncthreads();
        #pragma unroll
        for (int c = 0; c < 12; ++c) {
            int rr = rb * 384 + w * 48 + c * 4;
            int g = rr >> 10, j = rr & 1023;
            const float* Wp = (g == 0) ? Wz : ((g == 1) ? Wr : Wg);
            const float4* w0 = (const float4*)(Wp + (size_t)(j + 0) * Hz + kt * 256);
            const float4* w1 = (const float4*)(Wp + (size_t)(j + 1) * Hz + kt * 256);
            const float4* w2 = (const float4*)(Wp + (size_t)(j + 2) * Hz + kt * 256);
            const float4* w3 = (const float4*)(Wp + (size_t)(j + 3) * Hz + kt * 256);
            float a0 = acc[c * 4 + 0], a1 = acc[c * 4 + 1];
            float a2 = acc[c * 4 + 2], a3 = acc[c * 4 + 3];
            #pragma unroll 8
            for (int i4 = 0; i4 < 64; ++i4) {
                float h0v = xs[(i4 * 4 + 0) * 33 + lane];
                float h1v = xs[(i4 * 4 + 1) * 33 + lane];
                float h2v = xs[(i4 * 4 + 2) * 33 + lane];
                float h3v = xs[(i4 * 4 + 3) * 33 + lane];
                float4 q0 = w0[i4], q1 = w1[i4], q2 = w2[i4], q3 = w3[i4];
                a0 = fmaf(q0.x, h0v, a0); a0 = fmaf(q0.y, h1v, a0); a0 = fmaf(q0.z, h2v, a0); a0 = fmaf(q0.w, h3v, a0);
                a1 = fmaf(q1.x, h0v, a1); a1 = fmaf(q1.y, h1v, a1); a1 = fmaf(q1.z, h2v, a1); a1 = fmaf(q1.w, h3v, a1);
                a2 = fmaf(q2.x, h0v, a2); a2 = fmaf(q2.y, h1v, a2); a2 = fmaf(q2.z, h2v, a2); a2 = fmaf(q2.w, h3v, a2);
                a3 = fmaf(q3.x, h0v, a3); a3 = fmaf(q3.y, h1v, a3); a3 = fmaf(q3.z, h2v, a3); a3 = fmaf(q3.w, h3v, a3);
            }
            acc[c * 4 + 0] = a0; acc[c * 4 + 1] = a1;
            acc[c * 4 + 2] = a2; acc[c * 4 + 3] = a3;
        }
    }
    #pragma unroll
    for (int c = 0; c < 12; ++c) {
        int rr = rb * 384 + w * 48 + c * 4;
        int g = rr >> 10, j = rr & 1023;
        size_t base = (((size_t)g * Sz + s) * Hz + j) * Bz + lane;
        g_gates[base +  0] = acc[c * 4 + 0];
        g_gates[base + 32] = acc[c * 4 + 1];
        g_gates[base + 64] = acc[c * 4 + 2];
        g_gates[base + 96] = acc[c * 4 + 3];
    }
}

// ---------------------------------------------------------------------------
// scan v6: high-reuse warp mapping.
//   phase1: warp (half=w&1, sub=w>>1): 4 j x {z,r} = 8 accs, k-slice 32/tile
//           -> each h load feeds 8 ffma2
//   phase2: warp sub2=w: all 8 g rows = 8 accs, k-slice 16/tile
//           -> each h load feeds 8 ffma2, single h pass
// Double-buffered cp.async.cg staging (4 tiles x 32KB per phase),
// fence-free grid barrier, packed fp32x2 FFMA. 128 CTAs x 512 threads.
//
// SMEM (floats): buf0 8192 | buf1 8192 | ws 24576 | part 4096 = 45056 (176KB)
// ---------------------------------------------------------------------------
#define SCAN_SMEM_FLOATS (8192 + 8192 + 24576 + 4096)
#define TILE_FLOATS 8192   // 128 k-pairs x [b][2] = 32KB

__global__ void __launch_bounds__(TPBS, 1) scan_kernel(
    const float* __restrict__ Whz, const float* __restrict__ Whr, const float* __restrict__ Whg,
    const float* __restrict__ bz,  const float* __restrict__ br,  const float* __restrict__ bg,
    float* __restrict__ hid_out, int layer)
{
    extern __shared__ float smem[];
    float* bufs = smem;                    // 2 x 8192
    float* ws   = smem + 2 * TILE_FLOATS;  // 24576  (z:0-7, r:8-15, g:16-23)
    float* part = ws + 24576;              // [16 warps][8][32]

    const int tid = threadIdx.x, lane = tid & 31, w = tid >> 5;
    const int jbase = blockIdx.x * 8;
    const int ncta = (int)gridDim.x;

    unsigned sbase;
    asm("{.reg .u64 t; cvta.to.shared.u64 t, %1; cvt.u32.u64 %0, t;}"
        : "=r"(sbase) : "l"(smem));
    const unsigned buf_s[2] = { sbase, sbase + TILE_FLOATS * 4u };
    const unsigned cp_off = (unsigned)tid * 16u;

    // ---- preload weights (once per layer): 6144 float4 --------------------
    for (int idx = tid; idx < 6144; idx += TPBS) {
        int g  = idx >> 11;
        int r2 = idx & 2047;
        int jl = r2 >> 8;
        int k4 = r2 & 255;
        const float* W = (g == 0) ? Whz : ((g == 1) ? Whr : Whg);
        float4 v = *(const float4*)(W + (size_t)(jbase + jl) * Hz + k4 * 4);
        *(float4*)&ws[((g * 8 + jl) << 10) + k4 * 4] = v;
    }
    __syncthreads();

    // reduction identity (warps 0..7): thread owns (jr, bb)
    const int jr = w & 7;
    const int jg = jbase + jr;
    const int bb = lane;
    const float bzj = bz[jg], brj = br[jg], bgj = bg[jg];
    const size_t plane = (size_t)Sz * Hz * Bz;
    const int pidx = (jg >> 1) * 64 + 2 * bb + (jg & 1);

    // phase-1 mapping: half = w&1 (j rows half*4..half*4+3), sub = w>>1 (k-slice)
    const int half = w & 1, sub = w >> 1;
    const float* wz_[4], * wr_[4], * wg_[8];
    #pragma unroll
    for (int q = 0; q < 4; ++q) {
        wz_[q] = &ws[(0 + half * 4 + q) * 1024];
        wr_[q] = &ws[(8 + half * 4 + q) * 1024];
    }
    #pragma unroll
    for (int q = 0; q < 8; ++q) wg_[q] = &ws[(16 + q) * 1024];

    // h pointers (u64, lane-indexed) into each buffer
    const u64* hq1[2] = {
        (const u64*)&bufs[(sub * 16) * 64 + 2 * lane],
        (const u64*)&bufs[TILE_FLOATS + (sub * 16) * 64 + 2 * lane]
    };
    const u64* hq2[2] = {
        (const u64*)&bufs[(w * 8) * 64 + 2 * lane],
        (const u64*)&bufs[TILE_FLOATS + (w * 8) * 64 + 2 * lane]
    };

    for (int t = 0; t < Sz; ++t) {
        const size_t gb = ((size_t)t * Hz + jg) * Bz + bb;
        float gzv = 0.f, grv = 0.f, hv = 0.f, zg = 0.f, rg = 0.f;
        if (w < 8) {
            gzv = g_gates[gb];
            grv = g_gates[plane + gb];
            hv  = g_h[pidx];
        }

        // ================= phase 1: z, r, u = r*h =========================
        u64 az[4] = {0,0,0,0}, ar[4] = {0,0,0,0};
        #pragma unroll
        for (int c = 0; c < 4; ++c)
            cpa16(buf_s[0] + cp_off + c * 8192u, (const char*)g_h + cp_off + c * 8192u);
        cpa_commit();
        #pragma unroll
        for (int tl = 0; tl < 4; ++tl) {
            if (tl < 3) {
                const char* src = (const char*)(g_h + (tl + 1) * TILE_FLOATS);
                #pragma unroll
                for (int c = 0; c < 4; ++c)
                    cpa16(buf_s[(tl + 1) & 1] + cp_off + c * 8192u, src + cp_off + c * 8192u);
                cpa_commit();
                cpa_wait<1>();
            } else {
                cpa_wait<0>();
            }
            __syncthreads();
            const int kg = tl * 256 + sub * 32;   // global k offset of this warp's slice
            const u64* hb = hq1[tl & 1];
            #pragma unroll
            for (int ii = 0; ii < 8; ++ii) {
                u64 hA = hb[(2 * ii + 0) * 32];
                u64 hB = hb[(2 * ii + 1) * 32];
                #pragma unroll
                for (int q = 0; q < 4; ++q) {
                    ulonglong2 qz = ((const ulonglong2*)(wz_[q] + kg))[ii];
                    ulonglong2 qr = ((const ulonglong2*)(wr_[q] + kg))[ii];
                    ffma2(az[q], qz.x, hA); ffma2(az[q], qz.y, hB);
                    ffma2(ar[q], qr.x, hA); ffma2(ar[q], qr.y, hB);
                }
            }
            __syncthreads();
        }
        #pragma unroll
        for (int q = 0; q < 4; ++q) {
            part[(w * 8 + q) * 32 + lane]     = f2sum(az[q]);
            part[(w * 8 + 4 + q) * 32 + lane] = f2sum(ar[q]);
        }
        __syncthreads();

        if (w < 8) {
            const int rh = jr >> 2, jl = jr & 3;
            float zsum = 0.f, rsum = 0.f;
            #pragma unroll
            for (int sb = 0; sb < 8; ++sb) {
                int wi = sb * 2 + rh;
                zsum += part[(wi * 8 + jl) * 32 + bb];
                rsum += part[(wi * 8 + 4 + jl) * 32 + bb];
            }
            zg = sigmoidf_(zsum + gzv + bzj);
            rg = sigmoidf_(rsum + grv + brj);
            g_u[pidx] = rg * hv;
        }

        grid_bar(2 * t, ncta);

        float ggv = 0.f;
        if (w < 8) ggv = g_gates[2 * plane + gb];

        // ================= phase 2: g, h_new ==============================
        u64 ag[8] = {0,0,0,0,0,0,0,0};
        #pragma unroll
        for (int c = 0; c < 4; ++c)
            cpa16(buf_s[0] + cp_off + c * 8192u, (const char*)g_u + cp_off + c * 8192u);
        cpa_commit();
        #pragma unroll
        for (int tl = 0; tl < 4; ++tl) {
            if (tl < 3) {
                const char* src = (const char*)(g_u + (tl + 1) * TILE_FLOATS);
                #pragma unroll
                for (int c = 0; c < 4; ++c)
                    cpa16(buf_s[(tl + 1) & 1] + cp_off + c * 8192u, src + cp_off + c * 8192u);
                cpa_commit();
                cpa_wait<1>();
            } else {
                cpa_wait<0>();
            }
            __syncthreads();
            const int kg = tl * 256 + w * 16;     // this warp's 16-k slice
            const u64* hb = hq2[tl & 1];
            #pragma unroll
            for (int ii = 0; ii < 4; ++ii) {
                u64 hA = hb[(2 * ii + 0) * 32];
                u64 hB = hb[(2 * ii + 1) * 32];
                #pragma unroll
                for (int q = 0; q < 8; ++q) {
                    ulonglong2 qg = ((const ulonglong2*)(wg_[q] + kg))[ii];
                    ffma2(ag[q], qg.x, hA); ffma2(ag[q], qg.y, hB);
                }
            }
            __syncthreads();
        }
        #pragma unroll
        for (int q = 0; q < 8; ++q)
            part[(w * 8 + q) * 32 + lane] = f2sum(ag[q]);
        __syncthreads();

        if (w < 8) {
            float gsum = 0.f;
            #pragma unroll
            for (int sb = 0; sb < 16; ++sb)
                gsum += part[(sb * 8 + jr) * 32 + bb];
            float gv = tanhf(gsum + ggv + bgj);
            float hn = zg * hv + (1.0f - zg) * gv;
            g_h[pidx] = hn;
            g_seq[gb] = hn;
            if (t == Sz - 1) hid_out[bb * (2 * Hz) + layer * Hz + jg] = hn;
        }

        grid_bar(2 * t + 1, ncta);
    }
}

// ---------------------------------------------------------------------------
// projY: y[b][s][o] = sum_h seq[s][h][b] * Wy[o][h] + by[o]
// ---------------------------------------------------------------------------
__global__ void __launch_bounds__(TPB) projy_kernel(
    const float* __restrict__ Wy, const float* __restrict__ by, float* __restrict__ y)
{
    __shared__ float xs[256 * 33];
    const int s = blockIdx.x;
    const int tid = threadIdx.x, lane = tid & 31, w = tid >> 5;

    float acc[16];
    #pragma unroll
    for (int q = 0; q < 16; ++q) acc[q] = 0.f;

    for (int kt = 0; kt < 4; ++kt) {
        __syncthreads();
        #pragma unroll
        for (int rep = 0; rep < 32; ++rep) {
            int e = rep * 256 + tid;
            int i = e >> 5, b = e & 31;
            xs[i * 33 + b] = g_seq[((size_t)s * Hz + kt * 256 + i) * Bz + b];
        }
        __syncthreads();
        #pragma unroll
        for (int c = 0; c < 4; ++c) {
            int o = w * 16 + c * 4;
            const float4* w0 = (const float4*)(Wy + (size_t)(o + 0) * Hz + kt * 256);
            const float4* w1 = (const float4*)(Wy + (size_t)(o + 1) * Hz + kt * 256);
            const float4* w2 = (const float4*)(Wy + (size_t)(o + 2) * Hz + kt * 256);
            const float4* w3 = (const float4*)(Wy + (size_t)(o + 3) * Hz + kt * 256);
            float a0 = acc[c * 4 + 0], a1 = acc[c * 4 + 1];
            float a2 = acc[c * 4 + 2], a3 = acc[c * 4 + 3];
            #pragma unroll 8
            for (int i4 = 0; i4 < 64; ++i4) {
                float h0v = xs[(i4 * 4 + 0) * 33 + lane];
                float h1v = xs[(i4 * 4 + 1) * 33 + lane];
                float h2v = xs[(i4 * 4 + 2) * 33 + lane];
                float h3v = xs[(i4 * 4 + 3) * 33 + lane];
                float4 q0 = w0[i4], q1 = w1[i4], q2 = w2[i4], q3 = w3[i4];
                a0 = fmaf(q0.x, h0v, a0); a0 = fmaf(q0.y, h1v, a0); a0 = fmaf(q0.z, h2v, a0); a0 = fmaf(q0.w, h3v, a0);
                a1 = fmaf(q1.x, h0v, a1); a1 = fmaf(q1.y, h1v, a1); a1 = fmaf(q1.z, h2v, a1); a1 = fmaf(q1.w, h3v, a1);
                a2 = fmaf(q2.x, h0v, a2); a2 = fmaf(q2.y, h1v, a2); a2 = fmaf(q2.z, h2v, a2); a2 = fmaf(q2.w, h3v, a2);
                a3 = fmaf(q3.x, h0v, a3); a3 = fmaf(q3.y, h1v, a3); a3 = fmaf(q3.z, h2v, a3); a3 = fmaf(q3.w, h3v, a3);
            }
            acc[c * 4 + 0] = a0; acc[c * 4 + 1] = a1;
            acc[c * 4 + 2] = a2; acc[c * 4 + 3] = a3;
        }
    }
    #pragma unroll
    for (int c = 0; c < 4; ++c) {
        #pragma unroll
        for (int q = 0; q < 4; ++q) {
            int o = w * 16 + c * 4 + q;
            y[(size_t)lane * (Sz * Oz) + (size_t)s * Oz + o] = acc[c * 4 + q] + by[o];
        }
    }
}

// ---------------------------------------------------------------------------
extern "C" void kernel_launch(void* const* d_in, const int* in_sizes, int n_in,
                              void* d_out, int out_size) {
    (void)in_sizes; (void)n_in; (void)out_size;
    const float* x    = (const float*)d_in[0];
    const float* h0   = (const float*)d_in[1];
    const float* Wxz0 = (const float*)d_in[2];
    const float* Whz0 = (const float*)d_in[3];
    const float* bz0  = (const float*)d_in[4];
    const float* Wxr0 = (const float*)d_in[5];
    const float* Whr0 = (const float*)d_in[6];
    const float* br0  = (const float*)d_in[7];
    const float* Wxg0 = (const float*)d_in[8];
    const float* Whg0 = (const float*)d_in[9];
    const float* bg0  = (const float*)d_in[10];
    const float* Wxz1 = (const float*)d_in[11];
    const float* Whz1 = (const float*)d_in[12];
    const float* bz1  = (const float*)d_in[13];
    const float* Wxr1 = (const float*)d_in[14];
    const float* Whr1 = (const float*)d_in[15];
    const float* br1  = (const float*)d_in[16];
    const float* Wxg1 = (const float*)d_in[17];
    const float* Whg1 = (const float*)d_in[18];
    const float* bg1  = (const float*)d_in[19];
    const float* Wy   = (const float*)d_in[20];
    const float* by   = (const float*)d_in[21];

    float* y   = (float*)d_out;
    float* hid = (float*)d_out + (size_t)Bz * Sz * Oz;

    const int scan_smem = SCAN_SMEM_FLOATS * (int)sizeof(float);
    cudaFuncSetAttribute(scan_kernel, cudaFuncAttributeMaxDynamicSharedMemorySize, scan_smem);

    // Layer 0
    proj0_kernel<<<Sz, TPB>>>(x, Wxz0, Wxr0, Wxg0);
    prep_kernel<<<SCAN_GRID, TPB>>>(h0, 0);
    scan_kernel<<<SCAN_GRID, TPBS, scan_smem>>>(Whz0, Whr0, Whg0, bz0, br0, bg0, hid, 0);

    // Layer 1
    proj1_kernel<<<dim3(8, Sz), TPB>>>(Wxz1, Wxr1, Wxg1);
    prep_kernel<<<SCAN_GRID, TPB>>>(h0, 1);
    scan_kernel<<<SCAN_GRID, TPBS, scan_smem>>>(Whz1, Whr1, Whg1, bz1, br1, bg1, hid, 1);

    // Output head
    projy_kernel<<<Sz, TPB>>>(Wy, by, y);
}

// round 9
// speedup vs baseline: 1.1984x; 1.1984x over previous
#include <cuda_runtime.h>
#include <math.h>

// Problem sizes
#define Bz 32
#define Sz 512
#define Iz 128
#define Hz 1024
#define Oz 128
#define TPB 256
#define TPBS 512
#define SCAN_GRID 128

typedef unsigned long long u64;

// Scratch (device globals)
__device__ __align__(16) float g_gates[(size_t)3 * Sz * Hz * Bz];   // [gate][t][j][b]
__device__ __align__(16) float g_seq[(size_t)Sz * Hz * Bz];         // paired: [t][j/2][b][2]
__device__ __align__(16) float g_h[Hz * Bz];   // paired: [j/2][b][2] -> (j/2)*64 + 2b + (j&1)
__device__ __align__(16) float g_u[Hz * Bz];   // paired, same as g_h
__device__ int   g_bar[2 * Sz];
__device__ int   g_flag[2 * Sz];

__device__ __forceinline__ float sigmoidf_(float x) {
    return 1.0f / (1.0f + expf(-x));
}

// packed fp32x2 FMA: acc = a * b + acc
__device__ __forceinline__ void ffma2(u64& acc, u64 a, u64 b) {
    asm("fma.rn.f32x2 %0, %1, %2, %0;" : "+l"(acc) : "l"(a), "l"(b));
}
__device__ __forceinline__ float f2sum(u64 v) {
    float lo, hi;
    asm("mov.b64 {%0, %1}, %2;" : "=f"(lo), "=f"(hi) : "l"(v));
    return lo + hi;
}

// cp.async 16B, L1-bypass (.cg)
__device__ __forceinline__ void cpa16(unsigned s, const void* g) {
    asm volatile("cp.async.cg.shared.global [%0], [%1], 16;" :: "r"(s), "l"(g));
}
__device__ __forceinline__ void cpa_commit() {
    asm volatile("cp.async.commit_group;" ::: "memory");
}
template <int N>
__device__ __forceinline__ void cpa_wait() {
    asm volatile("cp.async.wait_group %0;" :: "n"(N) : "memory");
}

// Fence-free grid barrier: release-atomic arrive, single-writer release flag,
// acquire spin. All cross-CTA data reads bypass L1 (cp.async.cg).
__device__ __forceinline__ void grid_bar(int i, int ncta) {
    __syncthreads();
    if (threadIdx.x == 0) {
        int v;
        asm volatile("atom.release.gpu.global.add.s32 %0, [%1], 1;"
                     : "=r"(v) : "l"(&g_bar[i]) : "memory");
        if (v == ncta - 1) {
            asm volatile("st.release.gpu.global.s32 [%0], 1;"
                         :: "l"(&g_flag[i]) : "memory");
        } else {
            int f;
            do {
                asm volatile("ld.acquire.gpu.global.s32 %0, [%1];"
                             : "=r"(f) : "l"(&g_flag[i]) : "memory");
            } while (f == 0);
        }
    }
    __syncthreads();
}

// ---------------------------------------------------------------------------
// prep: init h state (paired layout) + zero barrier counters/flags
// ---------------------------------------------------------------------------
__global__ void prep_kernel(const float* __restrict__ h0, int layer) {
    int idx = blockIdx.x * TPB + threadIdx.x;
    int j = idx >> 5;
    int b = idx & 31;
    g_h[(j >> 1) * 64 + 2 * b + (j & 1)] = h0[b * (2 * Hz) + layer * Hz + j];
    if (idx < 2 * Sz) { g_bar[idx] = 0; g_flag[idx] = 0; }
}

// ---------------------------------------------------------------------------
// proj0: layer-0 input projections (K=128), reads x directly (small)
// ---------------------------------------------------------------------------
__global__ void __launch_bounds__(TPB) proj0_kernel(
    const float* __restrict__ x,
    const float* __restrict__ Wz, const float* __restrict__ Wr, const float* __restrict__ Wg)
{
    __shared__ float xs[Iz * 33];
    const int s = blockIdx.x;
    const int tid = threadIdx.x, lane = tid & 31, w = tid >> 5;

    #pragma unroll
    for (int rep = 0; rep < 16; ++rep) {
        int e = rep * 256 + tid;
        int b = e >> 7, i = e & 127;
        xs[i * 33 + b] = x[((size_t)b * Sz + s) * Iz + i];
    }
    __syncthreads();

    for (int c = 0; c < 96; ++c) {
        int rr = w * 384 + c * 4;
        int g = rr >> 10;
        int j = rr & 1023;
        const float* Wp = (g == 0) ? Wz : ((g == 1) ? Wr : Wg);
        const float4* w0 = (const float4*)(Wp + (size_t)(j + 0) * Iz);
        const float4* w1 = (const float4*)(Wp + (size_t)(j + 1) * Iz);
        const float4* w2 = (const float4*)(Wp + (size_t)(j + 2) * Iz);
        const float4* w3 = (const float4*)(Wp + (size_t)(j + 3) * Iz);
        float a0 = 0.f, a1 = 0.f, a2 = 0.f, a3 = 0.f;
        #pragma unroll 8
        for (int i4 = 0; i4 < 32; ++i4) {
            float h0v = xs[(i4 * 4 + 0) * 33 + lane];
            float h1v = xs[(i4 * 4 + 1) * 33 + lane];
            float h2v = xs[(i4 * 4 + 2) * 33 + lane];
            float h3v = xs[(i4 * 4 + 3) * 33 + lane];
            float4 q0 = w0[i4], q1 = w1[i4], q2 = w2[i4], q3 = w3[i4];
            a0 = fmaf(q0.x, h0v, a0); a0 = fmaf(q0.y, h1v, a0); a0 = fmaf(q0.z, h2v, a0); a0 = fmaf(q0.w, h3v, a0);
            a1 = fmaf(q1.x, h0v, a1); a1 = fmaf(q1.y, h1v, a1); a1 = fmaf(q1.z, h2v, a1); a1 = fmaf(q1.w, h3v, a1);
            a2 = fmaf(q2.x, h0v, a2); a2 = fmaf(q2.y, h1v, a2); a2 = fmaf(q2.z, h2v, a2); a2 = fmaf(q2.w, h3v, a2);
            a3 = fmaf(q3.x, h0v, a3); a3 = fmaf(q3.y, h1v, a3); a3 = fmaf(q3.z, h2v, a3); a3 = fmaf(q3.w, h3v, a3);
        }
        size_t base = (((size_t)g * Sz + s) * Hz + j) * Bz + lane;
        g_gates[base +  0] = a0;
        g_gates[base + 32] = a1;
        g_gates[base + 64] = a2;
        g_gates[base + 96] = a3;
    }
}

// ---------------------------------------------------------------------------
// proj1 v2: layer-1 input projections (K=1024) from paired g_seq.
// s-pair blocking (2 timesteps per CTA: weight LDG per MAC halved) +
// k-packed FFMA2 (FMA issue halved).
// grid (16 rowblocks, 256 s-pairs), 512 threads, 12 rows per warp.
// SMEM: two tiles [128 kp][32 b][2] = 2 x 8192 floats (64KB).
// ---------------------------------------------------------------------------
__global__ void __launch_bounds__(TPBS, 1) proj1_kernel(
    const float* __restrict__ Wz, const float* __restrict__ Wr, const float* __restrict__ Wg)
{
    __shared__ float xs[2 * 8192];
    const int rb = blockIdx.x;          // 0..15
    const int sp = blockIdx.y;          // 0..255
    const int s0 = 2 * sp, s1 = s0 + 1;
    const int tid = threadIdx.x, lane = tid & 31, w = tid >> 5;   // w: 0..15

    // 12 row pointers for this warp (row = rb*192 + w*12 + q)
    const float* wrow[12];
    #pragma unroll
    for (int q = 0; q < 12; ++q) {
        int rr = rb * 192 + w * 12 + q;
        int g = rr >> 10, j = rr & 1023;
        const float* Wp = (g == 0) ? Wz : ((g == 1) ? Wr : Wg);
        wrow[q] = Wp + (size_t)j * Hz;
    }

    u64 a0[12], a1[12];
    #pragma unroll
    for (int q = 0; q < 12; ++q) { a0[q] = 0ull; a1[q] = 0ull; }

    for (int kt = 0; kt < 4; ++kt) {
        __syncthreads();
        {   // linear float4 copies of the two paired tiles
            const float4* src0 = (const float4*)&g_seq[(size_t)s0 * (Hz * Bz) + kt * 8192];
            const float4* src1 = (const float4*)&g_seq[(size_t)s1 * (Hz * Bz) + kt * 8192];
            float4* d = (float4*)xs;
            #pragma unroll
            for (int r = 0; r < 4; ++r) d[r * TPBS + tid] = src0[r * TPBS + tid];
            #pragma unroll
            for (int r = 0; r < 4; ++r) d[2048 + r * TPBS + tid] = src1[r * TPBS + tid];
        }
        __syncthreads();

        const u64* h0q = (const u64*)&xs[2 * lane];
        const u64* h1q = (const u64*)&xs[8192 + 2 * lane];
        #pragma unroll 4
        for (int ii = 0; ii < 64; ++ii) {
            u64 hA0 = h0q[(2 * ii + 0) * 32];
            u64 hB0 = h0q[(2 * ii + 1) * 32];
            u64 hA1 = h1q[(2 * ii + 0) * 32];
            u64 hB1 = h1q[(2 * ii + 1) * 32];
            #pragma unroll
            for (int q = 0; q < 12; ++q) {
                ulonglong2 wq = ((const ulonglong2*)(wrow[q] + kt * 256))[ii];
                ffma2(a0[q], wq.x, hA0); ffma2(a0[q], wq.y, hB0);
                ffma2(a1[q], wq.x, hA1); ffma2(a1[q], wq.y, hB1);
            }
        }
    }

    #pragma unroll
    for (int q = 0; q < 12; ++q) {
        int rr = rb * 192 + w * 12 + q;
        int g = rr >> 10, j = rr & 1023;
        size_t b0 = (((size_t)g * Sz + s0) * Hz + j) * Bz + lane;
        size_t b1 = (((size_t)g * Sz + s1) * Hz + j) * Bz + lane;
        g_gates[b0] = f2sum(a0[q]);
        g_gates[b1] = f2sum(a1[q]);
    }
}

// ---------------------------------------------------------------------------
// scan v7: phase-1 single h pass (each warp: ALL 16 z/r rows over a 16-k
// slice). Double-buffered cp.async.cg staging, fence-free grid barrier,
// packed fp32x2 FFMA. 128 CTAs x 512 threads.
//
// SMEM (floats): buf0 8192 | buf1 8192 | ws 24576 | part 8192 = 49152 (192KB)
// ---------------------------------------------------------------------------
#define SCAN_SMEM_FLOATS (8192 + 8192 + 24576 + 8192)
#define TILE_FLOATS 8192   // 128 k-pairs x [b][2] = 32KB

__global__ void __launch_bounds__(TPBS, 1) scan_kernel(
    const float* __restrict__ Whz, const float* __restrict__ Whr, const float* __restrict__ Whg,
    const float* __restrict__ bz,  const float* __restrict__ br,  const float* __restrict__ bg,
    float* __restrict__ hid_out, int layer)
{
    extern __shared__ float smem[];
    float* bufs = smem;                    // 2 x 8192
    float* ws   = smem + 2 * TILE_FLOATS;  // 24576  (z:0-7, r:8-15, g:16-23)
    float* part = ws + 24576;              // phase1: [16 warps][16][32]; phase2: [16][8][32]

    const int tid = threadIdx.x, lane = tid & 31, w = tid >> 5;
    const int jbase = blockIdx.x * 8;
    const int ncta = (int)gridDim.x;

    unsigned sbase;
    asm("{.reg .u64 t; cvta.to.shared.u64 t, %1; cvt.u32.u64 %0, t;}"
        : "=r"(sbase) : "l"(smem));
    const unsigned buf_s[2] = { sbase, sbase + TILE_FLOATS * 4u };
    const unsigned cp_off = (unsigned)tid * 16u;

    // ---- preload weights (once per layer): 6144 float4 --------------------
    for (int idx = tid; idx < 6144; idx += TPBS) {
        int g  = idx >> 11;
        int r2 = idx & 2047;
        int jl = r2 >> 8;
        int k4 = r2 & 255;
        const float* W = (g == 0) ? Whz : ((g == 1) ? Whr : Whg);
        float4 v = *(const float4*)(W + (size_t)(jbase + jl) * Hz + k4 * 4);
        *(float4*)&ws[((g * 8 + jl) << 10) + k4 * 4] = v;
    }
    __syncthreads();

    // reduction identity (warps 0..7): thread owns (jr, bb)
    const int jr = w & 7;
    const int jg = jbase + jr;
    const int bb = lane;
    const float bzj = bz[jg], brj = br[jg], bgj = bg[jg];
    const size_t plane = (size_t)Sz * Hz * Bz;
    const int pidx = (jg >> 1) * 64 + 2 * bb + (jg & 1);

    // h pointers (u64, lane-indexed) into each buffer: both phases use the
    // same 16-k (8 kp) slice per warp.
    const u64* hq[2] = {
        (const u64*)&bufs[(w * 8) * 64 + 2 * lane],
        (const u64*)&bufs[TILE_FLOATS + (w * 8) * 64 + 2 * lane]
    };

    for (int t = 0; t < Sz; ++t) {
        const size_t gb = ((size_t)t * Hz + jg) * Bz + bb;
        // paired g_seq index for this (t, jg, bb)
        const size_t sgb = (((size_t)t * (Hz / 2) + (jg >> 1)) * Bz + bb) * 2 + (jg & 1);
        float gzv = 0.f, grv = 0.f, hv = 0.f, zg = 0.f, rg = 0.f;
        if (w < 8) {
            gzv = g_gates[gb];
            grv = g_gates[plane + gb];
            hv  = g_h[pidx];
        }

        // ================= phase 1: z, r, u = r*h =========================
        // warp covers ALL 16 z/r rows over its 16-k slice (single h pass)
        u64 az[8], ar[8];
        #pragma unroll
        for (int q = 0; q < 8; ++q) { az[q] = 0ull; ar[q] = 0ull; }
        #pragma unroll
        for (int c = 0; c < 4; ++c)
            cpa16(buf_s[0] + cp_off + c * 8192u, (const char*)g_h + cp_off + c * 8192u);
        cpa_commit();
        #pragma unroll
        for (int tl = 0; tl < 4; ++tl) {
            if (tl < 3) {
                const char* src = (const char*)(g_h + (tl + 1) * TILE_FLOATS);
                #pragma unroll
                for (int c = 0; c < 4; ++c)
                    cpa16(buf_s[(tl + 1) & 1] + cp_off + c * 8192u, src + cp_off + c * 8192u);
                cpa_commit();
                cpa_wait<1>();
            } else {
                cpa_wait<0>();
            }
            __syncthreads();
            const int kg = tl * 256 + w * 16;
            const u64* hb = hq[tl & 1];
            #pragma unroll
            for (int ii = 0; ii < 4; ++ii) {
                u64 hA = hb[(2 * ii + 0) * 32];
                u64 hB = hb[(2 * ii + 1) * 32];
                #pragma unroll
                for (int q = 0; q < 8; ++q) {
                    ulonglong2 qz = ((const ulonglong2*)&ws[q * 1024 + kg])[ii];
                    ulonglong2 qr = ((const ulonglong2*)&ws[(8 + q) * 1024 + kg])[ii];
                    ffma2(az[q], qz.x, hA); ffma2(az[q], qz.y, hB);
                    ffma2(ar[q], qr.x, hA); ffma2(ar[q], qr.y, hB);
                }
            }
            __syncthreads();
        }
        #pragma unroll
        for (int q = 0; q < 8; ++q) {
            part[(w * 16 + q) * 32 + lane]     = f2sum(az[q]);
            part[(w * 16 + 8 + q) * 32 + lane] = f2sum(ar[q]);
        }
        __syncthreads();

        if (w < 8) {
            float zsum = 0.f, rsum = 0.f;
            #pragma unroll
            for (int wi = 0; wi < 16; ++wi) {
                zsum += part[(wi * 16 + jr) * 32 + bb];
                rsum += part[(wi * 16 + 8 + jr) * 32 + bb];
            }
            zg = sigmoidf_(zsum + gzv + bzj);
            rg = sigmoidf_(rsum + grv + brj);
            g_u[pidx] = rg * hv;
        }

        grid_bar(2 * t, ncta);

        float ggv = 0.f;
        if (w < 8) ggv = g_gates[2 * plane + gb];

        // ================= phase 2: g, h_new ==============================
        u64 ag[8];
        #pragma unroll
        for (int q = 0; q < 8; ++q) ag[q] = 0ull;
        #pragma unroll
        for (int c = 0; c < 4; ++c)
            cpa16(buf_s[0] + cp_off + c * 8192u, (const char*)g_u + cp_off + c * 8192u);
        cpa_commit();
        #pragma unroll
        for (int tl = 0; tl < 4; ++tl) {
            if (tl < 3) {
                const char* src = (const char*)(g_u + (tl + 1) * TILE_FLOATS);
                #pragma unroll
                for (int c = 0; c < 4; ++c)
                    cpa16(buf_s[(tl + 1) & 1] + cp_off + c * 8192u, src + cp_off + c * 8192u);
                cpa_commit();
                cpa_wait<1>();
            } else {
                cpa_wait<0>();
            }
            __syncthreads();
            const int kg = tl * 256 + w * 16;
            const u64* hb = hq[tl & 1];
            #pragma unroll
            for (int ii = 0; ii < 4; ++ii) {
                u64 hA = hb[(2 * ii + 0) * 32];
                u64 hB = hb[(2 * ii + 1) * 32];
                #pragma unroll
                for (int q = 0; q < 8; ++q) {
                    ulonglong2 qg = ((const ulonglong2*)&ws[(16 + q) * 1024 + kg])[ii];
                    ffma2(ag[q], qg.x, hA); ffma2(ag[q], qg.y, hB);
                }
            }
            __syncthreads();
        }
        #pragma unroll
        for (int q = 0; q < 8; ++q)
            part[(w * 8 + q) * 32 + lane] = f2sum(ag[q]);
        __syncthreads();

        if (w < 8) {
            float gsum = 0.f;
            #pragma unroll
            for (int wi = 0; wi < 16; ++wi)
                gsum += part[(wi * 8 + jr) * 32 + bb];
            float gv = tanhf(gsum + ggv + bgj);
            float hn = zg * hv + (1.0f - zg) * gv;
            g_h[pidx] = hn;
            g_seq[sgb] = hn;
            if (t == Sz - 1) hid_out[bb * (2 * Hz) + layer * Hz + jg] = hn;
        }

        grid_bar(2 * t + 1, ncta);
    }
}

// ---------------------------------------------------------------------------
// projy v2: y[b][s][o] = sum_h seq(paired)[s][h][b] * Wy[o][h] + by[o]
// grid 512 (s), 256 threads, 16 o-rows/warp, k-packed FFMA2.
// ---------------------------------------------------------------------------
__global__ void __launch_bounds__(TPB) projy_kernel(
    const float* __restrict__ Wy, const float* __restrict__ by, float* __restrict__ y)
{
    __shared__ float xs[8192];
    const int s = blockIdx.x;
    const int tid = threadIdx.x, lane = tid & 31, w = tid >> 5;

    u64 acc[16];
    #pragma unroll
    for (int q = 0; q < 16; ++q) acc[q] = 0ull;

    for (int kt = 0; kt < 4; ++kt) {
        __syncthreads();
        {   // linear float4 copy of the paired tile
            const float4* src = (const float4*)&g_seq[(size_t)s * (Hz * Bz) + kt * 8192];
            float4* d = (float4*)xs;
            #pragma unroll
            for (int r = 0; r < 8; ++r) d[r * TPB + tid] = src[r * TPB + tid];
        }
        __syncthreads();

        const u64* hq = (const u64*)&xs[2 * lane];
        #pragma unroll 4
        for (int ii = 0; ii < 64; ++ii) {
            u64 hA = hq[(2 * ii + 0) * 32];
            u64 hB = hq[(2 * ii + 1) * 32];
            #pragma unroll
            for (int q = 0; q < 16; ++q) {
                int o = w * 16 + q;
                ulonglong2 wq = ((const ulonglong2*)(Wy + (size_t)o * Hz + kt * 256))[ii];
                ffma2(acc[q], wq.x, hA); ffma2(acc[q], wq.y, hB);
            }
        }
    }

    #pragma unroll
    for (int q = 0; q < 16; ++q) {
        int o = w * 16 + q;
        y[(size_t)lane * (Sz * Oz) + (size_t)s * Oz + o] = f2sum(acc[q]) + by[o];
    }
}

// ---------------------------------------------------------------------------
extern "C" void kernel_launch(void* const* d_in, const int* in_sizes, int n_in,
                              void* d_out, int out_size) {
    (void)in_sizes; (void)n_in; (void)out_size;
    const float* x    = (const float*)d_in[0];
    const float* h0   = (const float*)d_in[1];
    const float* Wxz0 = (const float*)d_in[2];
    const float* Whz0 = (const float*)d_in[3];
    const float* bz0  = (const float*)d_in[4];
    const float* Wxr0 = (const float*)d_in[5];
    const float* Whr0 = (const float*)d_in[6];
    const float* br0  = (const float*)d_in[7];
    const float* Wxg0 = (const float*)d_in[8];
    const float* Whg0 = (const float*)d_in[9];
    const float* bg0  = (const float*)d_in[10];
    const float* Wxz1 = (const float*)d_in[11];
    const float* Whz1 = (const float*)d_in[12];
    const float* bz1  = (const float*)d_in[13];
    const float* Wxr1 = (const float*)d_in[14];
    const float* Whr1 = (const float*)d_in[15];
    const float* br1  = (const float*)d_in[16];
    const float* Wxg1 = (const float*)d_in[17];
    const float* Whg1 = (const float*)d_in[18];
    const float* bg1  = (const float*)d_in[19];
    const float* Wy   = (const float*)d_in[20];
    const float* by   = (const float*)d_in[21];

    float* y   = (float*)d_out;
    float* hid = (float*)d_out + (size_t)Bz * Sz * Oz;

    const int scan_smem = SCAN_SMEM_FLOATS * (int)sizeof(float);
    cudaFuncSetAttribute(scan_kernel, cudaFuncAttributeMaxDynamicSharedMemorySize, scan_smem);

    // Layer 0
    proj0_kernel<<<Sz, TPB>>>(x, Wxz0, Wxr0, Wxg0);
    prep_kernel<<<SCAN_GRID, TPB>>>(h0, 0);
    scan_kernel<<<SCAN_GRID, TPBS, scan_smem>>>(Whz0, Whr0, Whg0, bz0, br0, bg0, hid, 0);

    // Layer 1
    proj1_kernel<<<dim3(16, Sz / 2), TPBS>>>(Wxz1, Wxr1, Wxg1);
    prep_kernel<<<SCAN_GRID, TPB>>>(h0, 1);
    scan_kernel<<<SCAN_GRID, TPBS, scan_smem>>>(Whz1, Whr1, Whg1, bz1, br1, bg1, hid, 1);

    // Output head
    projy_kernel<<<Sz, TPB>>>(Wy, by, y);
}

// round 10
// speedup vs baseline: 1.2345x; 1.0301x over previous
#include <cuda_runtime.h>
#include <math.h>

// Problem sizes
#define Bz 32
#define Sz 512
#define Iz 128
#define Hz 1024
#define Oz 128
#define TPB 256
#define TPBS 512
#define SCAN_GRID 128

typedef unsigned long long u64;

// Scratch (device globals)
__device__ __align__(16) float g_gates[(size_t)3 * Sz * Hz * Bz];   // [gate][t][j][b]
__device__ __align__(16) float g_seq[(size_t)Sz * Hz * Bz];         // paired: [t][j/2][b][2]
__device__ __align__(16) float g_h[Hz * Bz];   // paired: [j/2][b][2]
__device__ __align__(16) float g_u[Hz * Bz];   // paired
__device__ int   g_bar[2 * Sz];
__device__ int   g_flag[2 * Sz];

__device__ __forceinline__ float sigmoidf_(float x) {
    return 1.0f / (1.0f + expf(-x));
}

// packed fp32x2 FMA: acc = a * b + acc
__device__ __forceinline__ void ffma2(u64& acc, u64 a, u64 b) {
    asm("fma.rn.f32x2 %0, %1, %2, %0;" : "+l"(acc) : "l"(a), "l"(b));
}
__device__ __forceinline__ float f2sum(u64 v) {
    float lo, hi;
    asm("mov.b64 {%0, %1}, %2;" : "=f"(lo), "=f"(hi) : "l"(v));
    return lo + hi;
}

// cp.async 16B, L1-bypass (.cg)
__device__ __forceinline__ void cpa16(unsigned s, const void* g) {
    asm volatile("cp.async.cg.shared.global [%0], [%1], 16;" :: "r"(s), "l"(g));
}
__device__ __forceinline__ void cpa_commit() {
    asm volatile("cp.async.commit_group;" ::: "memory");
}
template <int N>
__device__ __forceinline__ void cpa_wait() {
    asm volatile("cp.async.wait_group %0;" :: "n"(N) : "memory");
}

// Fence-free grid barrier: release-atomic arrive, single-writer release flag,
// acquire spin with nanosleep backoff (frees issue slots / power).
__device__ __forceinline__ void grid_bar(int i, int ncta) {
    __syncthreads();
    if (threadIdx.x == 0) {
        int v;
        asm volatile("atom.release.gpu.global.add.s32 %0, [%1], 1;"
                     : "=r"(v) : "l"(&g_bar[i]) : "memory");
        if (v == ncta - 1) {
            asm volatile("st.release.gpu.global.s32 [%0], 1;"
                         :: "l"(&g_flag[i]) : "memory");
        } else {
            int f;
            for (;;) {
                asm volatile("ld.acquire.gpu.global.s32 %0, [%1];"
                             : "=r"(f) : "l"(&g_flag[i]) : "memory");
                if (f) break;
                __nanosleep(64);
            }
        }
    }
    __syncthreads();
}

// ---------------------------------------------------------------------------
// prep: init h state (paired layout) + zero barrier counters/flags
// ---------------------------------------------------------------------------
__global__ void prep_kernel(const float* __restrict__ h0, int layer) {
    int idx = blockIdx.x * TPB + threadIdx.x;
    int j = idx >> 5;
    int b = idx & 31;
    g_h[(j >> 1) * 64 + 2 * b + (j & 1)] = h0[b * (2 * Hz) + layer * Hz + j];
    if (idx < 2 * Sz) { g_bar[idx] = 0; g_flag[idx] = 0; }
}

// ---------------------------------------------------------------------------
// proj0 v2: layer-0 input projections (K=128). s-pair blocking + FFMA2.
// grid (16 rowblocks, 256 s-pairs), 512 threads, 12 rows/warp x 2 s.
// ---------------------------------------------------------------------------
__global__ void __launch_bounds__(TPBS, 1) proj0_kernel(
    const float* __restrict__ x,
    const float* __restrict__ Wz, const float* __restrict__ Wr, const float* __restrict__ Wg)
{
    __shared__ float xraw[2 * 32 * 132];   // [s2][b][i] pitch 132
    __shared__ float xs[2 * 4096];         // paired [s2][ip=64][b][2]
    const int rb = blockIdx.x;
    const int sp = blockIdx.y;
    const int s0 = 2 * sp;
    const int tid = threadIdx.x, lane = tid & 31, w = tid >> 5;

    // hop 1: coalesced global -> raw smem
    #pragma unroll
    for (int rep = 0; rep < 4; ++rep) {
        int row = rep * 16 + w;            // 0..63: s2 = row>>5, b = row&31
        int s2 = row >> 5, b = row & 31;
        float4 v = ((const float4*)(x + ((size_t)b * Sz + s0 + s2) * Iz))[lane];
        *(float4*)&xraw[(s2 * 32 + b) * 132 + 4 * lane] = v;
    }
    __syncthreads();
    // hop 2: raw -> paired (float2 writes, conflict-free)
    #pragma unroll
    for (int rep = 0; rep < 8; ++rep) {
        int e = rep * 512 + tid;           // e = s2*2048 + ip*32 + b
        int b = e & 31;
        int ip = (e >> 5) & 63;
        int s2 = e >> 11;
        float lo = xraw[(s2 * 32 + b) * 132 + 2 * ip];
        float hi = xraw[(s2 * 32 + b) * 132 + 2 * ip + 1];
        ((float2*)xs)[e] = make_float2(lo, hi);
    }
    __syncthreads();

    // 12 row pointers for this warp
    const float* wrow[12];
    #pragma unroll
    for (int q = 0; q < 12; ++q) {
        int rr = rb * 192 + w * 12 + q;
        int g = rr >> 10, j = rr & 1023;
        const float* Wp = (g == 0) ? Wz : ((g == 1) ? Wr : Wg);
        wrow[q] = Wp + (size_t)j * Iz;
    }

    u64 a0[12], a1[12];
    #pragma unroll
    for (int q = 0; q < 12; ++q) { a0[q] = 0ull; a1[q] = 0ull; }

    const u64* h0q = (const u64*)&xs[2 * lane];
    const u64* h1q = (const u64*)&xs[4096 + 2 * lane];
    #pragma unroll 4
    for (int ii = 0; ii < 32; ++ii) {
        u64 hA0 = h0q[(2 * ii + 0) * 32];
        u64 hB0 = h0q[(2 * ii + 1) * 32];
        u64 hA1 = h1q[(2 * ii + 0) * 32];
        u64 hB1 = h1q[(2 * ii + 1) * 32];
        #pragma unroll
        for (int q = 0; q < 12; ++q) {
            ulonglong2 wq = ((const ulonglong2*)wrow[q])[ii];
            ffma2(a0[q], wq.x, hA0); ffma2(a0[q], wq.y, hB0);
            ffma2(a1[q], wq.x, hA1); ffma2(a1[q], wq.y, hB1);
        }
    }

    #pragma unroll
    for (int q = 0; q < 12; ++q) {
        int rr = rb * 192 + w * 12 + q;
        int g = rr >> 10, j = rr & 1023;
        size_t b0 = (((size_t)g * Sz + s0)     * Hz + j) * Bz + lane;
        size_t b1 = (((size_t)g * Sz + s0 + 1) * Hz + j) * Bz + lane;
        g_gates[b0] = f2sum(a0[q]);
        g_gates[b1] = f2sum(a1[q]);
    }
}

// ---------------------------------------------------------------------------
// proj1 v2 (unchanged from R9): K=1024, s-pair blocking + FFMA2.
// ---------------------------------------------------------------------------
__global__ void __launch_bounds__(TPBS, 1) proj1_kernel(
    const float* __restrict__ Wz, const float* __restrict__ Wr, const float* __restrict__ Wg)
{
    __shared__ float xs[2 * 8192];
    const int rb = blockIdx.x;
    const int sp = blockIdx.y;
    const int s0 = 2 * sp, s1 = s0 + 1;
    const int tid = threadIdx.x, lane = tid & 31, w = tid >> 5;

    const float* wrow[12];
    #pragma unroll
    for (int q = 0; q < 12; ++q) {
        int rr = rb * 192 + w * 12 + q;
        int g = rr >> 10, j = rr & 1023;
        const float* Wp = (g == 0) ? Wz : ((g == 1) ? Wr : Wg);
        wrow[q] = Wp + (size_t)j * Hz;
    }

    u64 a0[12], a1[12];
    #pragma unroll
    for (int q = 0; q < 12; ++q) { a0[q] = 0ull; a1[q] = 0ull; }

    for (int kt = 0; kt < 4; ++kt) {
        __syncthreads();
        {
            const float4* src0 = (const float4*)&g_seq[(size_t)s0 * (Hz * Bz) + kt * 8192];
            const float4* src1 = (const float4*)&g_seq[(size_t)s1 * (Hz * Bz) + kt * 8192];
            float4* d = (float4*)xs;
            #pragma unroll
            for (int r = 0; r < 4; ++r) d[r * TPBS + tid] = src0[r * TPBS + tid];
            #pragma unroll
            for (int r = 0; r < 4; ++r) d[2048 + r * TPBS + tid] = src1[r * TPBS + tid];
        }
        __syncthreads();

        const u64* h0q = (const u64*)&xs[2 * lane];
        const u64* h1q = (const u64*)&xs[8192 + 2 * lane];
        #pragma unroll 4
        for (int ii = 0; ii < 64; ++ii) {
            u64 hA0 = h0q[(2 * ii + 0) * 32];
            u64 hB0 = h0q[(2 * ii + 1) * 32];
            u64 hA1 = h1q[(2 * ii + 0) * 32];
            u64 hB1 = h1q[(2 * ii + 1) * 32];
            #pragma unroll
            for (int q = 0; q < 12; ++q) {
                ulonglong2 wq = ((const ulonglong2*)(wrow[q] + kt * 256))[ii];
                ffma2(a0[q], wq.x, hA0); ffma2(a0[q], wq.y, hB0);
                ffma2(a1[q], wq.x, hA1); ffma2(a1[q], wq.y, hB1);
            }
        }
    }

    #pragma unroll
    for (int q = 0; q < 12; ++q) {
        int rr = rb * 192 + w * 12 + q;
        int g = rr >> 10, j = rr & 1023;
        size_t b0 = (((size_t)g * Sz + s0) * Hz + j) * Bz + lane;
        size_t b1 = (((size_t)g * Sz + s1) * Hz + j) * Bz + lane;
        g_gates[b0] = f2sum(a0[q]);
        g_gates[b1] = f2sum(a1[q]);
    }
}

// ---------------------------------------------------------------------------
// scan v8: ring-3 tile buffers (one sync per tile, no trailing sync),
// phase-1 tail reduction split across all 16 warps, nanosleep barrier spin.
// 128 CTAs x 512 threads.
//
// SMEM (floats): buf 3x8192 | ws 24576 | part 8192 = 57344 (224KB)
// ---------------------------------------------------------------------------
#define SCAN_SMEM_FLOATS (3 * 8192 + 24576 + 8192)
#define TILE_FLOATS 8192   // 128 k-pairs x [b][2] = 32KB

__global__ void __launch_bounds__(TPBS, 1) scan_kernel(
    const float* __restrict__ Whz, const float* __restrict__ Whr, const float* __restrict__ Whg,
    const float* __restrict__ bz,  const float* __restrict__ br,  const float* __restrict__ bg,
    float* __restrict__ hid_out, int layer)
{
    extern __shared__ float smem[];
    float* bufs = smem;                    // 3 x 8192
    float* ws   = smem + 3 * TILE_FLOATS;  // 24576  (z:0-7, r:8-15, g:16-23)
    float* part = ws + 24576;              // ph1: [16][16][32]; ph2: [16][8][32]

    const int tid = threadIdx.x, lane = tid & 31, w = tid >> 5;
    const int jbase = blockIdx.x * 8;
    const int ncta = (int)gridDim.x;

    unsigned sbase;
    asm("{.reg .u64 t; cvta.to.shared.u64 t, %1; cvt.u32.u64 %0, t;}"
        : "=r"(sbase) : "l"(smem));
    const unsigned buf_s[3] = { sbase, sbase + TILE_FLOATS * 4u, sbase + TILE_FLOATS * 8u };
    const unsigned cp_off = (unsigned)tid * 16u;

    // ---- preload weights (once per layer): 6144 float4 --------------------
    for (int idx = tid; idx < 6144; idx += TPBS) {
        int g  = idx >> 11;
        int r2 = idx & 2047;
        int jl = r2 >> 8;
        int k4 = r2 & 255;
        const float* W = (g == 0) ? Whz : ((g == 1) ? Whr : Whg);
        float4 v = *(const float4*)(W + (size_t)(jbase + jl) * Hz + k4 * 4);
        *(float4*)&ws[((g * 8 + jl) << 10) + k4 * 4] = v;
    }
    __syncthreads();

    const int jr = w & 7;
    const int jg = jbase + jr;
    const int bb = lane;
    const float bzj = bz[jg], brj = br[jg], bgj = bg[jg];
    const size_t plane = (size_t)Sz * Hz * Bz;
    const int pidx = (jg >> 1) * 64 + 2 * bb + (jg & 1);

    // per-warp h slice pointers for each of the 3 buffers
    const u64* hq[3] = {
        (const u64*)&bufs[0 * TILE_FLOATS + (w * 8) * 64 + 2 * lane],
        (const u64*)&bufs[1 * TILE_FLOATS + (w * 8) * 64 + 2 * lane],
        (const u64*)&bufs[2 * TILE_FLOATS + (w * 8) * 64 + 2 * lane]
    };

    for (int t = 0; t < Sz; ++t) {
        const size_t gb = ((size_t)t * Hz + jg) * Bz + bb;
        const size_t sgb = (((size_t)t * (Hz / 2) + (jg >> 1)) * Bz + bb) * 2 + (jg & 1);
        // prefetch (all warps; w<8 uses gzv, w>=8 uses grv; both use hv)
        float gzv = g_gates[gb];
        float grv = g_gates[plane + gb];
        float hv  = g_h[pidx];
        float zg = 0.f;

        // ================= phase 1: z, r, u = r*h =========================
        u64 az[8], ar[8];
        #pragma unroll
        for (int q = 0; q < 8; ++q) { az[q] = 0ull; ar[q] = 0ull; }
        #pragma unroll
        for (int c = 0; c < 4; ++c)
            cpa16(buf_s[0] + cp_off + c * 8192u, (const char*)g_h + cp_off + c * 8192u);
        cpa_commit();
        #pragma unroll
        for (int tl = 0; tl < 4; ++tl) {
            if (tl < 3) {
                const char* src = (const char*)(g_h + (tl + 1) * TILE_FLOATS);
                unsigned dst = buf_s[(tl + 1) % 3];
                #pragma unroll
                for (int c = 0; c < 4; ++c)
                    cpa16(dst + cp_off + c * 8192u, src + cp_off + c * 8192u);
                cpa_commit();
                cpa_wait<1>();
            } else {
                cpa_wait<0>();
            }
            __syncthreads();
            const int kg = tl * 256 + w * 16;
            const u64* hb = hq[tl % 3];
            #pragma unroll
            for (int ii = 0; ii < 4; ++ii) {
                u64 hA = hb[(2 * ii + 0) * 32];
                u64 hB = hb[(2 * ii + 1) * 32];
                #pragma unroll
                for (int q = 0; q < 8; ++q) {
                    ulonglong2 qz = ((const ulonglong2*)&ws[q * 1024 + kg])[ii];
                    ulonglong2 qr = ((const ulonglong2*)&ws[(8 + q) * 1024 + kg])[ii];
                    ffma2(az[q], qz.x, hA); ffma2(az[q], qz.y, hB);
                    ffma2(ar[q], qr.x, hA); ffma2(ar[q], qr.y, hB);
                }
            }
        }
        #pragma unroll
        for (int q = 0; q < 8; ++q) {
            part[(w * 16 + q) * 32 + lane]     = f2sum(az[q]);
            part[(w * 16 + 8 + q) * 32 + lane] = f2sum(ar[q]);
        }
        __syncthreads();

        // split tail: w<8 -> z gate (zg persists to phase 2); w>=8 -> r gate + u store
        if (w < 8) {
            float zsum = 0.f;
            #pragma unroll
            for (int wi = 0; wi < 16; ++wi)
                zsum += part[(wi * 16 + jr) * 32 + bb];
            zg = sigmoidf_(zsum + gzv + bzj);
        } else {
            float rsum = 0.f;
            #pragma unroll
            for (int wi = 0; wi < 16; ++wi)
                rsum += part[(wi * 16 + 8 + jr) * 32 + bb];
            float rg = sigmoidf_(rsum + grv + brj);
            g_u[pidx] = rg * hv;
        }

        grid_bar(2 * t, ncta);

        float ggv = 0.f;
        if (w < 8) ggv = g_gates[2 * plane + gb];

        // ================= phase 2: g, h_new ==============================
        u64 ag[8];
        #pragma unroll
        for (int q = 0; q < 8; ++q) ag[q] = 0ull;
        #pragma unroll
        for (int c = 0; c < 4; ++c)
            cpa16(buf_s[0] + cp_off + c * 8192u, (const char*)g_u + cp_off + c * 8192u);
        cpa_commit();
        #pragma unroll
        for (int tl = 0; tl < 4; ++tl) {
            if (tl < 3) {
                const char* src = (const char*)(g_u + (tl + 1) * TILE_FLOATS);
                unsigned dst = buf_s[(tl + 1) % 3];
                #pragma unroll
                for (int c = 0; c < 4; ++c)
                    cpa16(dst + cp_off + c * 8192u, src + cp_off + c * 8192u);
                cpa_commit();
                cpa_wait<1>();
            } else {
                cpa_wait<0>();
            }
            __syncthreads();
            const int kg = tl * 256 + w * 16;
            const u64* hb = hq[tl % 3];
            #pragma unroll
            for (int ii = 0; ii < 4; ++ii) {
                u64 hA = hb[(2 * ii + 0) * 32];
                u64 hB = hb[(2 * ii + 1) * 32];
                #pragma unroll
                for (int q = 0; q < 8; ++q) {
                    ulonglong2 qg = ((const ulonglong2*)&ws[(16 + q) * 1024 + kg])[ii];
                    ffma2(ag[q], qg.x, hA); ffma2(ag[q], qg.y, hB);
                }
            }
        }
        #pragma unroll
        for (int q = 0; q < 8; ++q)
            part[(w * 8 + q) * 32 + lane] = f2sum(ag[q]);
        __syncthreads();

        if (w < 8) {
            float gsum = 0.f;
            #pragma unroll
            for (int wi = 0; wi < 16; ++wi)
                gsum += part[(wi * 8 + jr) * 32 + bb];
            float gv = tanhf(gsum + ggv + bgj);
            float hn = zg * hv + (1.0f - zg) * gv;
            g_h[pidx] = hn;
            g_seq[sgb] = hn;
            if (t == Sz - 1) hid_out[bb * (2 * Hz) + layer * Hz + jg] = hn;
        }

        grid_bar(2 * t + 1, ncta);
    }
}

// ---------------------------------------------------------------------------
// projy v2 (unchanged from R9)
// ---------------------------------------------------------------------------
__global__ void __launch_bounds__(TPB) projy_kernel(
    const float* __restrict__ Wy, const float* __restrict__ by, float* __restrict__ y)
{
    __shared__ float xs[8192];
    const int s = blockIdx.x;
    const int tid = threadIdx.x, lane = tid & 31, w = tid >> 5;

    u64 acc[16];
    #pragma unroll
    for (int q = 0; q < 16; ++q) acc[q] = 0ull;

    for (int kt = 0; kt < 4; ++kt) {
        __syncthreads();
        {
            const float4* src = (const float4*)&g_seq[(size_t)s * (Hz * Bz) + kt * 8192];
            float4* d = (float4*)xs;
            #pragma unroll
            for (int r = 0; r < 8; ++r) d[r * TPB + tid] = src[r * TPB + tid];
        }
        __syncthreads();

        const u64* hq = (const u64*)&xs[2 * lane];
        #pragma unroll 4
        for (int ii = 0; ii < 64; ++ii) {
            u64 hA = hq[(2 * ii + 0) * 32];
            u64 hB = hq[(2 * ii + 1) * 32];
            #pragma unroll
            for (int q = 0; q < 16; ++q) {
                int o = w * 16 + q;
                ulonglong2 wq = ((const ulonglong2*)(Wy + (size_t)o * Hz + kt * 256))[ii];
                ffma2(acc[q], wq.x, hA); ffma2(acc[q], wq.y, hB);
            }
        }
    }

    #pragma unroll
    for (int q = 0; q < 16; ++q) {
        int o = w * 16 + q;
        y[(size_t)lane * (Sz * Oz) + (size_t)s * Oz + o] = f2sum(acc[q]) + by[o];
    }
}

// ---------------------------------------------------------------------------
extern "C" void kernel_launch(void* const* d_in, const int* in_sizes, int n_in,
                              void* d_out, int out_size) {
    (void)in_sizes; (void)n_in; (void)out_size;
    const float* x    = (const float*)d_in[0];
    const float* h0   = (const float*)d_in[1];
    const float* Wxz0 = (const float*)d_in[2];
    const float* Whz0 = (const float*)d_in[3];
    const float* bz0  = (const float*)d_in[4];
    const float* Wxr0 = (const float*)d_in[5];
    const float* Whr0 = (const float*)d_in[6];
    const float* br0  = (const float*)d_in[7];
    const float* Wxg0 = (const float*)d_in[8];
    const float* Whg0 = (const float*)d_in[9];
    const float* bg0  = (const float*)d_in[10];
    const float* Wxz1 = (const float*)d_in[11];
    const float* Whz1 = (const float*)d_in[12];
    const float* bz1  = (const float*)d_in[13];
    const float* Wxr1 = (const float*)d_in[14];
    const float* Whr1 = (const float*)d_in[15];
    const float* br1  = (const float*)d_in[16];
    const float* Wxg1 = (const float*)d_in[17];
    const float* Whg1 = (const float*)d_in[18];
    const float* bg1  = (const float*)d_in[19];
    const float* Wy   = (const float*)d_in[20];
    const float* by   = (const float*)d_in[21];

    float* y   = (float*)d_out;
    float* hid = (float*)d_out + (size_t)Bz * Sz * Oz;

    const int scan_smem = SCAN_SMEM_FLOATS * (int)sizeof(float);
    cudaFuncSetAttribute(scan_kernel, cudaFuncAttributeMaxDynamicSharedMemorySize, scan_smem);

    // Layer 0
    proj0_kernel<<<dim3(16, Sz / 2), TPBS>>>(x, Wxz0, Wxr0, Wxg0);
    prep_kernel<<<SCAN_GRID, TPB>>>(h0, 0);
    scan_kernel<<<SCAN_GRID, TPBS, scan_smem>>>(Whz0, Whr0, Whg0, bz0, br0, bg0, hid, 0);

    // Layer 1
    proj1_kernel<<<dim3(16, Sz / 2), TPBS>>>(Wxz1, Wxr1, Wxg1);
    prep_kernel<<<SCAN_GRID, TPB>>>(h0, 1);
    scan_kernel<<<SCAN_GRID, TPBS, scan_smem>>>(Whz1, Whr1, Whg1, bz1, br1, bg1, hid, 1);

    // Output head
    projy_kernel<<<Sz, TPB>>>(Wy, by, y);
}

// round 11
// speedup vs baseline: 1.3151x; 1.0653x over previous
#include <cuda_runtime.h>
#include <math.h>

// Problem sizes
#define Bz 32
#define Sz 512
#define Iz 128
#define Hz 1024
#define Oz 128
#define TPB 256
#define TPBS 512
#define SCAN_GRID 128

typedef unsigned long long u64;

// Scratch (device globals)
__device__ __align__(16) float g_gates[(size_t)3 * Sz * Hz * Bz];   // [gate][t][j][b]
__device__ __align__(16) float g_seq[(size_t)Sz * Hz * Bz];         // paired: [t][j/2][b][2]
__device__ __align__(16) float g_h[Hz * Bz];   // paired: [j/2][b][2]
__device__ __align__(16) float g_u[Hz * Bz];   // paired
__device__ int   g_bar[2 * Sz];
__device__ int   g_flag[2 * Sz];

__device__ __forceinline__ float sigmoidf_(float x) {
    return 1.0f / (1.0f + expf(-x));
}

// packed fp32x2 FMA: acc = a * b + acc
__device__ __forceinline__ void ffma2(u64& acc, u64 a, u64 b) {
    asm("fma.rn.f32x2 %0, %1, %2, %0;" : "+l"(acc) : "l"(a), "l"(b));
}
__device__ __forceinline__ float f2sum(u64 v) {
    float lo, hi;
    asm("mov.b64 {%0, %1}, %2;" : "=f"(lo), "=f"(hi) : "l"(v));
    return lo + hi;
}

// Fence-free grid barrier: release-atomic arrive, single-writer release flag,
// acquire spin with nanosleep backoff.
__device__ __forceinline__ void grid_bar(int i, int ncta) {
    __syncthreads();
    if (threadIdx.x == 0) {
        int v;
        asm volatile("atom.release.gpu.global.add.s32 %0, [%1], 1;"
                     : "=r"(v) : "l"(&g_bar[i]) : "memory");
        if (v == ncta - 1) {
            asm volatile("st.release.gpu.global.s32 [%0], 1;"
                         :: "l"(&g_flag[i]) : "memory");
        } else {
            int f;
            for (;;) {
                asm volatile("ld.acquire.gpu.global.s32 %0, [%1];"
                             : "=r"(f) : "l"(&g_flag[i]) : "memory");
                if (f) break;
                __nanosleep(64);
            }
        }
    }
    __syncthreads();
}

// ---------------------------------------------------------------------------
// prep: init h state (paired layout) + zero barrier counters/flags
// ---------------------------------------------------------------------------
__global__ void prep_kernel(const float* __restrict__ h0, int layer) {
    int idx = blockIdx.x * TPB + threadIdx.x;
    int j = idx >> 5;
    int b = idx & 31;
    g_h[(j >> 1) * 64 + 2 * b + (j & 1)] = h0[b * (2 * Hz) + layer * Hz + j];
    if (idx < 2 * Sz) { g_bar[idx] = 0; g_flag[idx] = 0; }
}

// ---------------------------------------------------------------------------
// proj0 v2: layer-0 input projections (K=128). s-pair blocking + FFMA2.
// ---------------------------------------------------------------------------
__global__ void __launch_bounds__(TPBS, 1) proj0_kernel(
    const float* __restrict__ x,
    const float* __restrict__ Wz, const float* __restrict__ Wr, const float* __restrict__ Wg)
{
    __shared__ float xraw[2 * 32 * 132];   // [s2][b][i] pitch 132
    __shared__ float xs[2 * 4096];         // paired [s2][ip=64][b][2]
    const int rb = blockIdx.x;
    const int sp = blockIdx.y;
    const int s0 = 2 * sp;
    const int tid = threadIdx.x, lane = tid & 31, w = tid >> 5;

    #pragma unroll
    for (int rep = 0; rep < 4; ++rep) {
        int row = rep * 16 + w;
        int s2 = row >> 5, b = row & 31;
        float4 v = ((const float4*)(x + ((size_t)b * Sz + s0 + s2) * Iz))[lane];
        *(float4*)&xraw[(s2 * 32 + b) * 132 + 4 * lane] = v;
    }
    __syncthreads();
    #pragma unroll
    for (int rep = 0; rep < 8; ++rep) {
        int e = rep * 512 + tid;
        int b = e & 31;
        int ip = (e >> 5) & 63;
        int s2 = e >> 11;
        float lo = xraw[(s2 * 32 + b) * 132 + 2 * ip];
        float hi = xraw[(s2 * 32 + b) * 132 + 2 * ip + 1];
        ((float2*)xs)[e] = make_float2(lo, hi);
    }
    __syncthreads();

    const float* wrow[12];
    #pragma unroll
    for (int q = 0; q < 12; ++q) {
        int rr = rb * 192 + w * 12 + q;
        int g = rr >> 10, j = rr & 1023;
        const float* Wp = (g == 0) ? Wz : ((g == 1) ? Wr : Wg);
        wrow[q] = Wp + (size_t)j * Iz;
    }

    u64 a0[12], a1[12];
    #pragma unroll
    for (int q = 0; q < 12; ++q) { a0[q] = 0ull; a1[q] = 0ull; }

    const u64* h0q = (const u64*)&xs[2 * lane];
    const u64* h1q = (const u64*)&xs[4096 + 2 * lane];
    #pragma unroll 4
    for (int ii = 0; ii < 32; ++ii) {
        u64 hA0 = h0q[(2 * ii + 0) * 32];
        u64 hB0 = h0q[(2 * ii + 1) * 32];
        u64 hA1 = h1q[(2 * ii + 0) * 32];
        u64 hB1 = h1q[(2 * ii + 1) * 32];
        #pragma unroll
        for (int q = 0; q < 12; ++q) {
            ulonglong2 wq = ((const ulonglong2*)wrow[q])[ii];
            ffma2(a0[q], wq.x, hA0); ffma2(a0[q], wq.y, hB0);
            ffma2(a1[q], wq.x, hA1); ffma2(a1[q], wq.y, hB1);
        }
    }

    #pragma unroll
    for (int q = 0; q < 12; ++q) {
        int rr = rb * 192 + w * 12 + q;
        int g = rr >> 10, j = rr & 1023;
        size_t b0 = (((size_t)g * Sz + s0)     * Hz + j) * Bz + lane;
        size_t b1 = (((size_t)g * Sz + s0 + 1) * Hz + j) * Bz + lane;
        g_gates[b0] = f2sum(a0[q]);
        g_gates[b1] = f2sum(a1[q]);
    }
}

// ---------------------------------------------------------------------------
// proj1 v2: K=1024, s-pair blocking + FFMA2 (unchanged).
// ---------------------------------------------------------------------------
__global__ void __launch_bounds__(TPBS, 1) proj1_kernel(
    const float* __restrict__ Wz, const float* __restrict__ Wr, const float* __restrict__ Wg)
{
    __shared__ float xs[2 * 8192];
    const int rb = blockIdx.x;
    const int sp = blockIdx.y;
    const int s0 = 2 * sp, s1 = s0 + 1;
    const int tid = threadIdx.x, lane = tid & 31, w = tid >> 5;

    const float* wrow[12];
    #pragma unroll
    for (int q = 0; q < 12; ++q) {
        int rr = rb * 192 + w * 12 + q;
        int g = rr >> 10, j = rr & 1023;
        const float* Wp = (g == 0) ? Wz : ((g == 1) ? Wr : Wg);
        wrow[q] = Wp + (size_t)j * Hz;
    }

    u64 a0[12], a1[12];
    #pragma unroll
    for (int q = 0; q < 12; ++q) { a0[q] = 0ull; a1[q] = 0ull; }

    for (int kt = 0; kt < 4; ++kt) {
        __syncthreads();
        {
            const float4* src0 = (const float4*)&g_seq[(size_t)s0 * (Hz * Bz) + kt * 8192];
            const float4* src1 = (const float4*)&g_seq[(size_t)s1 * (Hz * Bz) + kt * 8192];
            float4* d = (float4*)xs;
            #pragma unroll
            for (int r = 0; r < 4; ++r) d[r * TPBS + tid] = src0[r * TPBS + tid];
            #pragma unroll
            for (int r = 0; r < 4; ++r) d[2048 + r * TPBS + tid] = src1[r * TPBS + tid];
        }
        __syncthreads();

        const u64* h0q = (const u64*)&xs[2 * lane];
        const u64* h1q = (const u64*)&xs[8192 + 2 * lane];
        #pragma unroll 4
        for (int ii = 0; ii < 64; ++ii) {
            u64 hA0 = h0q[(2 * ii + 0) * 32];
            u64 hB0 = h0q[(2 * ii + 1) * 32];
            u64 hA1 = h1q[(2 * ii + 0) * 32];
            u64 hB1 = h1q[(2 * ii + 1) * 32];
            #pragma unroll
            for (int q = 0; q < 12; ++q) {
                ulonglong2 wq = ((const ulonglong2*)(wrow[q] + kt * 256))[ii];
                ffma2(a0[q], wq.x, hA0); ffma2(a0[q], wq.y, hB0);
                ffma2(a1[q], wq.x, hA1); ffma2(a1[q], wq.y, hB1);
            }
        }
    }

    #pragma unroll
    for (int q = 0; q < 12; ++q) {
        int rr = rb * 192 + w * 12 + q;
        int g = rr >> 10, j = rr & 1023;
        size_t b0 = (((size_t)g * Sz + s0) * Hz + j) * Bz + lane;
        size_t b1 = (((size_t)g * Sz + s1) * Hz + j) * Bz + lane;
        g_gates[b0] = f2sum(a0[q]);
        g_gates[b1] = f2sum(a1[q]);
    }
}

// ---------------------------------------------------------------------------
// scan v9: NO smem staging. Each warp owns a 64-k slice (32 k-pairs) and
// reads h/u for it directly from L2 via __ldcg (each element consumed by
// exactly one warp -> staging bought nothing). 6 syncs/step total.
// 128 CTAs x 512 threads.
//
// SMEM (floats): ws 24576 | part 8192 = 32768 (128KB)
// ---------------------------------------------------------------------------
#define SCAN_SMEM_FLOATS (24576 + 8192)

__global__ void __launch_bounds__(TPBS, 1) scan_kernel(
    const float* __restrict__ Whz, const float* __restrict__ Whr, const float* __restrict__ Whg,
    const float* __restrict__ bz,  const float* __restrict__ br,  const float* __restrict__ bg,
    float* __restrict__ hid_out, int layer)
{
    extern __shared__ float smem[];
    float* ws   = smem;            // 24576  (z:0-7, r:8-15, g:16-23)
    float* part = smem + 24576;    // ph1: [16][16][32]; ph2: [16][8][32]

    const int tid = threadIdx.x, lane = tid & 31, w = tid >> 5;
    const int jbase = blockIdx.x * 8;
    const int ncta = (int)gridDim.x;

    // ---- preload weights (once per layer): 6144 float4 --------------------
    for (int idx = tid; idx < 6144; idx += TPBS) {
        int g  = idx >> 11;
        int r2 = idx & 2047;
        int jl = r2 >> 8;
        int k4 = r2 & 255;
        const float* W = (g == 0) ? Whz : ((g == 1) ? Whr : Whg);
        float4 v = *(const float4*)(W + (size_t)(jbase + jl) * Hz + k4 * 4);
        *(float4*)&ws[((g * 8 + jl) << 10) + k4 * 4] = v;
    }
    __syncthreads();

    const int jr = w & 7;
    const int jg = jbase + jr;
    const int bb = lane;
    const float bzj = bz[jg], brj = br[jg], bgj = bg[jg];
    const size_t plane = (size_t)Sz * Hz * Bz;
    const int pidx = (jg >> 1) * 64 + 2 * bb + (jg & 1);

    // this warp's k-slice: k-pairs [w*32, w*32+32), lane-indexed u64 view
    const u64* hp1 = (const u64*)g_h + (size_t)(w * 32) * 32 + lane;
    const u64* hp2 = (const u64*)g_u + (size_t)(w * 32) * 32 + lane;
    const int kg = w * 64;   // float offset of slice within a weight row

    for (int t = 0; t < Sz; ++t) {
        const size_t gb = ((size_t)t * Hz + jg) * Bz + bb;
        const size_t sgb = (((size_t)t * (Hz / 2) + (jg >> 1)) * Bz + bb) * 2 + (jg & 1);
        float gzv = g_gates[gb];
        float grv = g_gates[plane + gb];
        float hv  = g_h[pidx];
        float zg = 0.f;

        // ================= phase 1: z, r, u = r*h =========================
        u64 az[8], ar[8];
        #pragma unroll
        for (int q = 0; q < 8; ++q) { az[q] = 0ull; ar[q] = 0ull; }
        #pragma unroll
        for (int ii = 0; ii < 16; ++ii) {
            u64 hA = __ldcg(hp1 + (2 * ii + 0) * 32);
            u64 hB = __ldcg(hp1 + (2 * ii + 1) * 32);
            #pragma unroll
            for (int q = 0; q < 8; ++q) {
                ulonglong2 qz = ((const ulonglong2*)&ws[q * 1024 + kg])[ii];
                ulonglong2 qr = ((const ulonglong2*)&ws[(8 + q) * 1024 + kg])[ii];
                ffma2(az[q], qz.x, hA); ffma2(az[q], qz.y, hB);
                ffma2(ar[q], qr.x, hA); ffma2(ar[q], qr.y, hB);
            }
        }
        #pragma unroll
        for (int q = 0; q < 8; ++q) {
            part[(w * 16 + q) * 32 + lane]     = f2sum(az[q]);
            part[(w * 16 + 8 + q) * 32 + lane] = f2sum(ar[q]);
        }
        __syncthreads();

        // split tail: w<8 -> z gate (zg persists); w>=8 -> r gate + u store
        if (w < 8) {
            float zsum = 0.f;
            #pragma unroll
            for (int wi = 0; wi < 16; ++wi)
                zsum += part[(wi * 16 + jr) * 32 + bb];
            zg = sigmoidf_(zsum + gzv + bzj);
        } else {
            float rsum = 0.f;
            #pragma unroll
            for (int wi = 0; wi < 16; ++wi)
                rsum += part[(wi * 16 + 8 + jr) * 32 + bb];
            float rg = sigmoidf_(rsum + grv + brj);
            g_u[pidx] = rg * hv;
        }

        grid_bar(2 * t, ncta);

        float ggv = 0.f;
        if (w < 8) ggv = g_gates[2 * plane + gb];

        // ================= phase 2: g, h_new ==============================
        u64 ag[8];
        #pragma unroll
        for (int q = 0; q < 8; ++q) ag[q] = 0ull;
        #pragma unroll
        for (int ii = 0; ii < 16; ++ii) {
            u64 hA = __ldcg(hp2 + (2 * ii + 0) * 32);
            u64 hB = __ldcg(hp2 + (2 * ii + 1) * 32);
            #pragma unroll
            for (int q = 0; q < 8; ++q) {
                ulonglong2 qg = ((const ulonglong2*)&ws[(16 + q) * 1024 + kg])[ii];
                ffma2(ag[q], qg.x, hA); ffma2(ag[q], qg.y, hB);
            }
        }
        #pragma unroll
        for (int q = 0; q < 8; ++q)
            part[(w * 8 + q) * 32 + lane] = f2sum(ag[q]);
        __syncthreads();

        if (w < 8) {
            float gsum = 0.f;
            #pragma unroll
            for (int wi = 0; wi < 16; ++wi)
                gsum += part[(wi * 8 + jr) * 32 + bb];
            float gv = tanhf(gsum + ggv + bgj);
            float hn = zg * hv + (1.0f - zg) * gv;
            g_h[pidx] = hn;
            g_seq[sgb] = hn;
            if (t == Sz - 1) hid_out[bb * (2 * Hz) + layer * Hz + jg] = hn;
        }

        grid_bar(2 * t + 1, ncta);
    }
}

// ---------------------------------------------------------------------------
// projy v2 (unchanged)
// ---------------------------------------------------------------------------
__global__ void __launch_bounds__(TPB) projy_kernel(
    const float* __restrict__ Wy, const float* __restrict__ by, float* __restrict__ y)
{
    __shared__ float xs[8192];
    const int s = blockIdx.x;
    const int tid = threadIdx.x, lane = tid & 31, w = tid >> 5;

    u64 acc[16];
    #pragma unroll
    for (int q = 0; q < 16; ++q) acc[q] = 0ull;

    for (int kt = 0; kt < 4; ++kt) {
        __syncthreads();
        {
            const float4* src = (const float4*)&g_seq[(size_t)s * (Hz * Bz) + kt * 8192];
            float4* d = (float4*)xs;
            #pragma unroll
            for (int r = 0; r < 8; ++r) d[r * TPB + tid] = src[r * TPB + tid];
        }
        __syncthreads();

        const u64* hq = (const u64*)&xs[2 * lane];
        #pragma unroll 4
        for (int ii = 0; ii < 64; ++ii) {
            u64 hA = hq[(2 * ii + 0) * 32];
            u64 hB = hq[(2 * ii + 1) * 32];
            #pragma unroll
            for (int q = 0; q < 16; ++q) {
                int o = w * 16 + q;
                ulonglong2 wq = ((const ulonglong2*)(Wy + (size_t)o * Hz + kt * 256))[ii];
                ffma2(acc[q], wq.x, hA); ffma2(acc[q], wq.y, hB);
            }
        }
    }

    #pragma unroll
    for (int q = 0; q < 16; ++q) {
        int o = w * 16 + q;
        y[(size_t)lane * (Sz * Oz) + (size_t)s * Oz + o] = f2sum(acc[q]) + by[o];
    }
}

// ---------------------------------------------------------------------------
extern "C" void kernel_launch(void* const* d_in, const int* in_sizes, int n_in,
                              void* d_out, int out_size) {
    (void)in_sizes; (void)n_in; (void)out_size;
    const float* x    = (const float*)d_in[0];
    const float* h0   = (const float*)d_in[1];
    const float* Wxz0 = (const float*)d_in[2];
    const float* Whz0 = (const float*)d_in[3];
    const float* bz0  = (const float*)d_in[4];
    const float* Wxr0 = (const float*)d_in[5];
    const float* Whr0 = (const float*)d_in[6];
    const float* br0  = (const float*)d_in[7];
    const float* Wxg0 = (const float*)d_in[8];
    const float* Whg0 = (const float*)d_in[9];
    const float* bg0  = (const float*)d_in[10];
    const float* Wxz1 = (const float*)d_in[11];
    const float* Whz1 = (const float*)d_in[12];
    const float* bz1  = (const float*)d_in[13];
    const float* Wxr1 = (const float*)d_in[14];
    const float* Whr1 = (const float*)d_in[15];
    const float* br1  = (const float*)d_in[16];
    const float* Wxg1 = (const float*)d_in[17];
    const float* Whg1 = (const float*)d_in[18];
    const float* bg1  = (const float*)d_in[19];
    const float* Wy   = (const float*)d_in[20];
    const float* by   = (const float*)d_in[21];

    float* y   = (float*)d_out;
    float* hid = (float*)d_out + (size_t)Bz * Sz * Oz;

    const int scan_smem = SCAN_SMEM_FLOATS * (int)sizeof(float);
    cudaFuncSetAttribute(scan_kernel, cudaFuncAttributeMaxDynamicSharedMemorySize, scan_smem);

    // Layer 0
    proj0_kernel<<<dim3(16, Sz / 2), TPBS>>>(x, Wxz0, Wxr0, Wxg0);
    prep_kernel<<<SCAN_GRID, TPB>>>(h0, 0);
    scan_kernel<<<SCAN_GRID, TPBS, scan_smem>>>(Whz0, Whr0, Whg0, bz0, br0, bg0, hid, 0);

    // Layer 1
    proj1_kernel<<<dim3(16, Sz / 2), TPBS>>>(Wxz1, Wxr1, Wxg1);
    prep_kernel<<<SCAN_GRID, TPB>>>(h0, 1);
    scan_kernel<<<SCAN_GRID, TPBS, scan_smem>>>(Whz1, Whr1, Whg1, bz1, br1, bg1, hid, 1);

    // Output head
    projy_kernel<<<Sz, TPB>>>(Wy, by, y);
}